// round 1
// baseline (speedup 1.0000x reference)
#include <cuda_runtime.h>

#define EMB 64
#define NN_MAX 160000
#define NE_MAX 4000000

// Scratch (static __device__ globals — no allocation at runtime)
__device__ float g_bufA[NN_MAX * EMB];          // 40.96 MB
__device__ float g_bufB[NN_MAX * EMB];          // 40.96 MB
__device__ int   g_rowstart[NN_MAX + 1];
__device__ int   g_cursor[NN_MAX];              // counts, then placement cursors
__device__ int   g_scol[NE_MAX];                // row-sorted col indices
__device__ float g_sval[NE_MAX];                // row-sorted edge weights

// ---------------------------------------------------------------------------
// 1) init: bufA = concat(user_emb, news_emb); out(=acc) = same; zero counts
// ---------------------------------------------------------------------------
__global__ void init_kernel(const float4* __restrict__ ue,
                            const float4* __restrict__ ne,
                            float4* __restrict__ out,
                            int n_user4, int n_total4, int nn)
{
    int i = blockIdx.x * blockDim.x + threadIdx.x;
    if (i < n_total4) {
        float4 v = (i < n_user4) ? ue[i] : ne[i - n_user4];
        reinterpret_cast<float4*>(g_bufA)[i] = v;
        out[i] = v;
    }
    if (i < nn) g_cursor[i] = 0;
}

// ---------------------------------------------------------------------------
// 2) count edges per destination row
// ---------------------------------------------------------------------------
__global__ void count_kernel(const int* __restrict__ erow, int ne)
{
    int e = blockIdx.x * blockDim.x + threadIdx.x;
    if (e < ne) atomicAdd(&g_cursor[erow[e]], 1);
}

// ---------------------------------------------------------------------------
// 3) single-block exclusive scan over nn counts -> rowstart; cursor = rowstart
// ---------------------------------------------------------------------------
__global__ void scan_kernel(int nn)
{
    __shared__ int s[1024];
    int t = threadIdx.x;
    int ch = (nn + 1023) / 1024;
    int base = t * ch;

    int sum = 0;
    for (int i = 0; i < ch; i++) {
        int idx = base + i;
        if (idx < nn) sum += g_cursor[idx];
    }
    s[t] = sum;
    __syncthreads();

    // Hillis-Steele inclusive scan of 1024 partials
    for (int off = 1; off < 1024; off <<= 1) {
        int v = (t >= off) ? s[t - off] : 0;
        __syncthreads();
        s[t] += v;
        __syncthreads();
    }

    int run = (t == 0) ? 0 : s[t - 1];
    for (int i = 0; i < ch; i++) {
        int idx = base + i;
        if (idx < nn) {
            int c = g_cursor[idx];
            g_rowstart[idx] = run;
            g_cursor[idx]   = run;   // becomes the placement cursor
            run += c;
        }
    }
    if (t == 1023) g_rowstart[nn] = s[1023];
}

// ---------------------------------------------------------------------------
// 4) place edges into row-sorted arrays
// ---------------------------------------------------------------------------
__global__ void place_kernel(const int* __restrict__ erow,
                             const int* __restrict__ ecol,
                             const float* __restrict__ eval_,
                             int ne)
{
    int e = blockIdx.x * blockDim.x + threadIdx.x;
    if (e < ne) {
        int r = erow[e];
        int p = atomicAdd(&g_cursor[r], 1);
        g_scol[p] = ecol[e];
        g_sval[p] = eval_[e];
    }
}

// ---------------------------------------------------------------------------
// 5) SPMM: one warp per row. lane owns dims [2*lane, 2*lane+1] as float2.
//    next = S * cur ; acc += next ; last layer: acc = (acc + S*cur) * inv
// ---------------------------------------------------------------------------
__global__ __launch_bounds__(256)
void spmm_kernel(float* __restrict__ out,
                 int srcB, int dstB, int isLast, float invL, int nn)
{
    int gtid = blockIdx.x * blockDim.x + threadIdx.x;
    int w    = gtid >> 5;
    int lane = gtid & 31;
    if (w >= nn) return;

    const float2* __restrict__ src =
        reinterpret_cast<const float2*>(srcB ? g_bufB : g_bufA);

    int s = g_rowstart[w];
    int t = g_rowstart[w + 1];

    float ax = 0.f, ay = 0.f;
    int e = s;
    for (; e + 4 <= t; e += 4) {
        int   c0 = g_scol[e + 0], c1 = g_scol[e + 1];
        int   c2 = g_scol[e + 2], c3 = g_scol[e + 3];
        float w0 = g_sval[e + 0], w1 = g_sval[e + 1];
        float w2 = g_sval[e + 2], w3 = g_sval[e + 3];
        float2 v0 = __ldg(&src[c0 * 32 + lane]);
        float2 v1 = __ldg(&src[c1 * 32 + lane]);
        float2 v2 = __ldg(&src[c2 * 32 + lane]);
        float2 v3 = __ldg(&src[c3 * 32 + lane]);
        ax += w0 * v0.x; ay += w0 * v0.y;
        ax += w1 * v1.x; ay += w1 * v1.y;
        ax += w2 * v2.x; ay += w2 * v2.y;
        ax += w3 * v3.x; ay += w3 * v3.y;
    }
    for (; e < t; e++) {
        int   c = g_scol[e];
        float wv = g_sval[e];
        float2 v = __ldg(&src[c * 32 + lane]);
        ax += wv * v.x; ay += wv * v.y;
    }

    float2* o2  = reinterpret_cast<float2*>(out);
    int     idx = w * 32 + lane;
    float2  prev = o2[idx];
    if (isLast) {
        o2[idx] = make_float2((prev.x + ax) * invL, (prev.y + ay) * invL);
    } else {
        float2* dst = reinterpret_cast<float2*>(dstB ? g_bufB : g_bufA);
        dst[idx] = make_float2(ax, ay);
        o2[idx]  = make_float2(prev.x + ax, prev.y + ay);
    }
}

// ---------------------------------------------------------------------------
extern "C" void kernel_launch(void* const* d_in, const int* in_sizes, int n_in,
                              void* d_out, int out_size)
{
    const float* ue = (const float*)d_in[0];   // user_emb  [n_users, 64]
    const float* ne = (const float*)d_in[1];   // news_emb  [n_items, 64]
    const float* ev = (const float*)d_in[2];   // edge_val  [ne]
    const int*   er = (const int*)  d_in[3];   // edge_row  [ne]
    const int*   ec = (const int*)  d_in[4];   // edge_col  [ne]
    // d_in[5] = n_layers (scalar); fixed at 3 for this problem.

    int n_users = in_sizes[0] / EMB;
    int n_items = in_sizes[1] / EMB;
    int nn      = n_users + n_items;
    int nedge   = in_sizes[2];

    int n_user4  = n_users * (EMB / 4);
    int n_total4 = nn * (EMB / 4);

    const int T = 256;
    float* out = (float*)d_out;

    init_kernel<<<(n_total4 + T - 1) / T, T>>>(
        (const float4*)ue, (const float4*)ne, (float4*)d_out,
        n_user4, n_total4, nn);

    count_kernel<<<(nedge + T - 1) / T, T>>>(er, nedge);
    scan_kernel<<<1, 1024>>>(nn);
    place_kernel<<<(nedge + T - 1) / T, T>>>(er, ec, ev, nedge);

    int warpThreads = nn * 32;
    int blocks = (warpThreads + T - 1) / T;
    const float inv = 0.25f;   // 1 / (n_layers + 1), n_layers = 3

    spmm_kernel<<<blocks, T>>>(out, /*srcB=*/0, /*dstB=*/1, /*isLast=*/0, inv, nn);
    spmm_kernel<<<blocks, T>>>(out, /*srcB=*/1, /*dstB=*/0, /*isLast=*/0, inv, nn);
    spmm_kernel<<<blocks, T>>>(out, /*srcB=*/0, /*dstB=*/0, /*isLast=*/1, inv, nn);
}